// round 4
// baseline (speedup 1.0000x reference)
#include <cuda_runtime.h>
#include <cstdint>

// Problem dims (fixed)
#define B_ 128
#define C_ 16
#define F_ 128
#define D_ 512

// Scratch (no allocation allowed) — normalized c_feats and reciprocal norms of f_feats rows
__device__ float g_xn[2048 * 512];   // (B*C, D) normalized
__device__ float g_rnf[128 * 128];   // 1/||f_feats[n,f]||

// ---------------------------------------------------------------------------
// Kernel A: row norms. rows 0..2047 -> normalize c_feats into g_xn;
// rows 2048..18431 -> store 1/norm of f_feats row.
// ---------------------------------------------------------------------------
__global__ void prep_kernel(const float* __restrict__ cf, const float* __restrict__ ff) {
    int row = blockIdx.x;
    int t = threadIdx.x;  // 128 threads, 4 floats each (one float4)
    const float* src = (row < 2048) ? (cf + (size_t)row * D_)
                                    : (ff + (size_t)(row - 2048) * D_);
    float4 v = ((const float4*)src)[t];
    float ss = v.x * v.x + v.y * v.y + v.z * v.z + v.w * v.w;
#pragma unroll
    for (int o = 16; o > 0; o >>= 1) ss += __shfl_xor_sync(0xffffffffu, ss, o);
    __shared__ float sred[4];
    if ((t & 31) == 0) sred[t >> 5] = ss;
    __syncthreads();
    float tot = sred[0] + sred[1] + sred[2] + sred[3];
    float nrm = sqrtf(tot);
    if (row < 2048) {
        float4 o;
        o.x = v.x / nrm; o.y = v.y / nrm; o.z = v.z / nrm; o.w = v.w / nrm;
        ((float4*)(g_xn + (size_t)row * D_))[t] = o;
    } else if (t == 0) {
        g_rnf[row - 2048] = 1.0f / nrm;
    }
}

// ---------------------------------------------------------------------------
// Kernel B: fused GEMM (128x128 tile, K=512) + per-pair DTW + backtrack + mask
// Grid: (n=128, mblk=16). Block 256 threads = 8 warps; warp w owns pair
// (m = mblk*8 + w, n).
// ---------------------------------------------------------------------------
struct SmemLayout {
    float As[16][128];                 // 8 KB (K-major transposed A tile)
    float Bs[16][128];                 // 8 KB
    float S[128][128];                 // 64 KB: S tile, later reused as mask
    unsigned char mvb[8][16][32];      // 4 KB: 2-bit moves, 4 per byte
    float rnf_s[16];                   // only f<=15 ever needs rescale
};

__global__ void __launch_bounds__(256, 2)
dtw_kernel(const float* __restrict__ ff, float* __restrict__ out) {
    extern __shared__ char smraw[];
    SmemLayout& sm = *reinterpret_cast<SmemLayout*>(smraw);

    const int tid = threadIdx.x;
    const int n = blockIdx.x, mblk = blockIdx.y;
    const int tr = tid >> 4, tc = tid & 15;

    if (tid < 16) sm.rnf_s[tid] = g_rnf[n * F_ + tid];

    const float* Ag = g_xn + (size_t)mblk * 128 * D_;
    const float* Bg = ff + (size_t)n * F_ * D_;

    float acc[8][8];
#pragma unroll
    for (int i = 0; i < 8; i++)
#pragma unroll
        for (int j = 0; j < 8; j++) acc[i][j] = 0.0f;

    for (int kt = 0; kt < 32; kt++) {
        const int kbase = kt * 16;
#pragma unroll
        for (int q = 0; q < 2; q++) {
            int e = tid + q * 256;
            int r = e >> 2, kq = e & 3;
            float4 av = *(const float4*)(Ag + (size_t)r * D_ + kbase + kq * 4);
            float4 bv = *(const float4*)(Bg + (size_t)r * D_ + kbase + kq * 4);
            int k0 = kq * 4;
            sm.As[k0 + 0][r] = av.x; sm.As[k0 + 1][r] = av.y;
            sm.As[k0 + 2][r] = av.z; sm.As[k0 + 3][r] = av.w;
            sm.Bs[k0 + 0][r] = bv.x; sm.Bs[k0 + 1][r] = bv.y;
            sm.Bs[k0 + 2][r] = bv.z; sm.Bs[k0 + 3][r] = bv.w;
        }
        __syncthreads();
#pragma unroll
        for (int k = 0; k < 16; k++) {
            float a[8], b[8];
            *(float4*)&a[0] = *(const float4*)&sm.As[k][tr * 8];
            *(float4*)&a[4] = *(const float4*)&sm.As[k][tr * 8 + 4];
            *(float4*)&b[0] = *(const float4*)&sm.Bs[k][tc * 8];
            *(float4*)&b[4] = *(const float4*)&sm.Bs[k][tc * 8 + 4];
#pragma unroll
            for (int i = 0; i < 8; i++)
#pragma unroll
                for (int j = 0; j < 8; j++)
                    acc[i][j] = fmaf(a[i], b[j], acc[i][j]);
        }
        __syncthreads();
    }

    // Epilogue: S[c,f] = raw * (f<=c ? 1/||f_row|| : 1). Rows tr*8..tr*8+7 of
    // warp w's own 16-row slab (tr in {2w,2w+1}) -> no block sync needed after.
#pragma unroll
    for (int i = 0; i < 8; i++) {
        int row = tr * 8 + i;
        int c = row & 15;
#pragma unroll
        for (int j = 0; j < 8; j++) {
            int f = tc * 8 + j;
            float v = acc[i][j];
            if (f <= c) v *= sm.rnf_s[f];
            sm.S[row][f] = v;
        }
    }
    __syncwarp();

    // ---- DTW DP (reference's row-parallel form), one warp per pair ----
    const int w = tid >> 5, lane = tid & 31;
    const float NEG = __int_as_float(0xff800000);  // -inf
    float Rp[4] = {NEG, NEG, NEG, NEG};            // D[i-1] at my 4 cols
    float p_prev = 0.0f;                            // padded col-0 of prev row
    float (*Srows)[128] = (float (*)[128]) & sm.S[w * 16][0];

    for (int i = 1; i <= 16; i++) {
        float4 sv = *(const float4*)&Srows[i - 1][lane * 4];
        // local inclusive cumsum
        float cl0 = sv.x, cl1 = cl0 + sv.y, cl2 = cl1 + sv.z, cl3 = cl2 + sv.w;
        float inc = cl3;
#pragma unroll
        for (int d = 1; d < 32; d <<= 1) {
            float tsh = __shfl_up_sync(0xffffffffu, inc, d);
            if (lane >= d) inc += tsh;
        }
        float ex = __shfl_up_sync(0xffffffffu, inc, 1);
        if (lane == 0) ex = 0.0f;
        float Cc0 = ex + cl0, Cc1 = ex + cl1, Cc2 = ex + cl2, Cc3 = ex + cl3;
        // A[j] = max(D[i-1,j], D[i-1,j-1])
        float rp_left = __shfl_up_sync(0xffffffffu, Rp[3], 1);
        if (lane == 0) rp_left = p_prev;
        float A0 = fmaxf(Rp[0], rp_left);
        float A1 = fmaxf(Rp[1], Rp[0]);
        float A2 = fmaxf(Rp[2], Rp[1]);
        float A3 = fmaxf(Rp[3], Rp[2]);
        // T = A - Cm1, local cummax
        float M0 = A0 - ex;
        float M1 = fmaxf(M0, A1 - Cc0);
        float M2 = fmaxf(M1, A2 - Cc1);
        float M3 = fmaxf(M2, A3 - Cc2);
        float mscan = M3;
#pragma unroll
        for (int d = 1; d < 32; d <<= 1) {
            float tsh = __shfl_up_sync(0xffffffffu, mscan, d);
            if (lane >= d) mscan = fmaxf(mscan, tsh);
        }
        float exm = __shfl_up_sync(0xffffffffu, mscan, 1);
        if (lane == 0) exm = NEG;
        float Rc[4];
        Rc[0] = Cc0 + fmaxf(M0, exm);
        Rc[1] = Cc1 + fmaxf(M1, exm);
        Rc[2] = Cc2 + fmaxf(M2, exm);
        Rc[3] = Cc3 + fmaxf(M3, exm);
        // mv = argmax(up, left, diag), first-max priority (matches jnp.argmax)
        float rc_left = __shfl_up_sync(0xffffffffu, Rc[3], 1);
        if (lane == 0) rc_left = NEG;  // padded col-0 of current row
        unsigned int byte = 0;
#pragma unroll
        for (int u = 0; u < 4; u++) {
            float up = Rp[u];
            float left = (u == 0) ? rc_left : Rc[u - 1];
            float dg = (u == 0) ? rp_left : Rp[u - 1];
            int m;
            if (up >= left && up >= dg) m = 0;
            else if (left >= dg) m = 1;
            else m = 2;
            byte |= (unsigned)m << (2 * u);
        }
        sm.mvb[w][i - 1][lane] = (unsigned char)byte;
        Rp[0] = Rc[0]; Rp[1] = Rc[1]; Rp[2] = Rc[2]; Rp[3] = Rc[3];
        p_prev = NEG;
    }
    __syncwarp();

    // Zero mask (reuse S slab), then lane 0 backtracks writing 1.0
    float4* mreg = (float4*)&Srows[0][0];
    for (int t2 = lane; t2 < 512; t2 += 32) mreg[t2] = make_float4(0.f, 0.f, 0.f, 0.f);
    __syncwarp();
    if (lane == 0) {
        int i = 16, j = 128;
        while (i > 0 && j > 0) {
            Srows[i - 1][j - 1] = 1.0f;
            unsigned int byte = sm.mvb[w][i - 1][(j - 1) >> 2];
            int m = (byte >> (2 * ((j - 1) & 3))) & 3;
            if (m == 0) i -= 1;
            else if (m == 1) j -= 1;
            else { i -= 1; j -= 1; }
        }
    }
    __syncwarp();

    // Coalesced store: out[m][n][c][f]
    int mglob = mblk * 8 + w;
    float* outp = out + (((size_t)mglob * 128 + n) * 16) * 128;
    const float4* srcp = (const float4*)&Srows[0][0];
    float4* dstp = (float4*)outp;
    for (int t2 = lane; t2 < 512; t2 += 32) dstp[t2] = srcp[t2];
}

// ---------------------------------------------------------------------------
extern "C" void kernel_launch(void* const* d_in, const int* in_sizes, int n_in,
                              void* d_out, int out_size) {
    const float* cf = (const float*)d_in[0];  // c_feats [128,16,512]
    const float* ff = (const float*)d_in[1];  // f_feats [128,128,512]
    float* out = (float*)d_out;               // [128,128,16,128] float32

    prep_kernel<<<18432, 128>>>(cf, ff);

    cudaFuncSetAttribute(dtw_kernel, cudaFuncAttributeMaxDynamicSharedMemorySize,
                         (int)sizeof(SmemLayout));
    dim3 grid(128, 16);
    dtw_kernel<<<grid, 256, (int)sizeof(SmemLayout)>>>(ff, out);
}

// round 5
// speedup vs baseline: 1.2208x; 1.2208x over previous
#include <cuda_runtime.h>
#include <cstdint>

// Problem dims (fixed)
#define B_ 128
#define C_ 16
#define F_ 128
#define D_ 512

// Scratch (no allocation allowed)
__device__ float g_xnT[512 * 2048];        // normalized c_feats, TRANSPOSED: [k][m]
__device__ float g_ffT[128 * 512 * 128];   // f_feats transposed per n: [n][k][f]
__device__ float g_rnc[2048];              // 1/||c_feats row||
__device__ float g_rnf[128 * 128];         // 1/||f_feats[n,f]||

// ---------------------------------------------------------------------------
// Kernel A: reciprocal row norms for both tensors.
// ---------------------------------------------------------------------------
__global__ void prep_norms(const float* __restrict__ cf, const float* __restrict__ ff) {
    int row = blockIdx.x;
    int t = threadIdx.x;  // 128 threads, one float4 each
    const float* src = (row < 2048) ? (cf + (size_t)row * D_)
                                    : (ff + (size_t)(row - 2048) * D_);
    float4 v = ((const float4*)src)[t];
    float ss = v.x * v.x + v.y * v.y + v.z * v.z + v.w * v.w;
#pragma unroll
    for (int o = 16; o > 0; o >>= 1) ss += __shfl_xor_sync(0xffffffffu, ss, o);
    __shared__ float sred[4];
    if ((t & 31) == 0) sred[t >> 5] = ss;
    __syncthreads();
    if (t == 0) {
        float nrm = sqrtf(sred[0] + sred[1] + sred[2] + sred[3]);
        if (row < 2048) g_rnc[row] = 1.0f / nrm;
        else            g_rnf[row - 2048] = 1.0f / nrm;
    }
}

// ---------------------------------------------------------------------------
// Kernel B1: transpose + normalize c_feats -> g_xnT [512][2048]
// grid (16, 64), block (32, 8)
// ---------------------------------------------------------------------------
__global__ void transpose_c(const float* __restrict__ cf) {
    __shared__ float t[32][33];
    int kbase = blockIdx.x * 32, mbase = blockIdx.y * 32;
    int tx = threadIdx.x, ty = threadIdx.y;
#pragma unroll
    for (int i = 0; i < 4; i++) {
        int m = mbase + ty + i * 8;
        t[ty + i * 8][tx] = cf[(size_t)m * D_ + kbase + tx] * g_rnc[m];
    }
    __syncthreads();
#pragma unroll
    for (int i = 0; i < 4; i++) {
        g_xnT[(size_t)(kbase + ty + i * 8) * 2048 + mbase + tx] = t[tx][ty + i * 8];
    }
}

// ---------------------------------------------------------------------------
// Kernel B2: transpose f_feats per n -> g_ffT [n][512][128]
// grid (16, 4, 128), block (32, 8)
// ---------------------------------------------------------------------------
__global__ void transpose_f(const float* __restrict__ ff) {
    __shared__ float t[32][33];
    int kbase = blockIdx.x * 32, fbase = blockIdx.y * 32, n = blockIdx.z;
    int tx = threadIdx.x, ty = threadIdx.y;
    const float* fin = ff + (size_t)n * F_ * D_;
    float* fout = g_ffT + (size_t)n * D_ * F_;
#pragma unroll
    for (int i = 0; i < 4; i++) {
        t[ty + i * 8][tx] = fin[(size_t)(fbase + ty + i * 8) * D_ + kbase + tx];
    }
    __syncthreads();
#pragma unroll
    for (int i = 0; i < 4; i++) {
        fout[(size_t)(kbase + ty + i * 8) * F_ + fbase + tx] = t[tx][ty + i * 8];
    }
}

// ---------------------------------------------------------------------------
// Kernel C: GEMM (cp.async double-buffered) + per-pair DTW + backtrack + mask
// Grid: (n=128, mblk=16). Block 256 threads = 8 warps; warp w owns pair
// (m = mblk*8 + w, n).
// ---------------------------------------------------------------------------
struct SmemLayout {
    float As[2][16][128];              // 16 KB double-buffered (k-major)
    float Bs[2][16][128];              // 16 KB
    float S[128][128];                 // 64 KB: S tile, later reused as mask
    unsigned char mvb[8][16][32];      // 4 KB: 2-bit moves
    float rnf_s[16];
};

__device__ __forceinline__ void cp_async16(float* sp, const float* gp) {
    unsigned sa = (unsigned)__cvta_generic_to_shared(sp);
    asm volatile("cp.async.cg.shared.global [%0], [%1], 16;\n" ::"r"(sa), "l"(gp));
}

__global__ void __launch_bounds__(256, 2)
dtw_kernel(float* __restrict__ out) {
    extern __shared__ char smraw[];
    SmemLayout& sm = *reinterpret_cast<SmemLayout*>(smraw);

    const int tid = threadIdx.x;
    const int n = blockIdx.x, mblk = blockIdx.y;
    const int tr = tid >> 4, tc = tid & 15;

    if (tid < 16) sm.rnf_s[tid] = g_rnf[n * F_ + tid];

    const float* An = g_xnT + mblk * 128;              // + k*2048 + m
    const float* Bn = g_ffT + (size_t)n * D_ * F_;     // + k*128 + f

    // stage tile kt into buffer buf: 1024 16B segments, 4 per thread
    auto stage = [&](int buf, int kt) {
        const int kbase = kt * 16;
#pragma unroll
        for (int s = 0; s < 4; s++) {
            int idx = tid + s * 256;
            int r = idx >> 5;       // 0..31 (uniform per warp)
            int seg = idx & 31;     // 16B segment within a 512B row
            if (r < 16) {
                cp_async16(&sm.As[buf][r][seg * 4],
                           An + (size_t)(kbase + r) * 2048 + seg * 4);
            } else {
                int rr = r - 16;
                cp_async16(&sm.Bs[buf][rr][seg * 4],
                           Bn + (size_t)(kbase + rr) * 128 + seg * 4);
            }
        }
        asm volatile("cp.async.commit_group;\n" ::);
    };

    float acc[8][8];
#pragma unroll
    for (int i = 0; i < 8; i++)
#pragma unroll
        for (int j = 0; j < 8; j++) acc[i][j] = 0.0f;

    stage(0, 0);

    for (int kt = 0; kt < 32; kt++) {
        const int buf = kt & 1;
        if (kt + 1 < 32) {
            stage(buf ^ 1, kt + 1);
            asm volatile("cp.async.wait_group 1;\n" ::);
        } else {
            asm volatile("cp.async.wait_group 0;\n" ::);
        }
        __syncthreads();
#pragma unroll
        for (int k = 0; k < 16; k++) {
            float a[8], b[8];
            *(float4*)&a[0] = *(const float4*)&sm.As[buf][k][tr * 8];
            *(float4*)&a[4] = *(const float4*)&sm.As[buf][k][tr * 8 + 4];
            *(float4*)&b[0] = *(const float4*)&sm.Bs[buf][k][tc * 8];
            *(float4*)&b[4] = *(const float4*)&sm.Bs[buf][k][tc * 8 + 4];
#pragma unroll
            for (int i = 0; i < 8; i++)
#pragma unroll
                for (int j = 0; j < 8; j++)
                    acc[i][j] = fmaf(a[i], b[j], acc[i][j]);
        }
        __syncthreads();
    }

    // Epilogue: S[c,f] = raw * (f<=c ? 1/||f_row|| : 1). Each warp's rows stay
    // within its own 16-row slab (tr in {2w,2w+1}) -> only __syncwarp needed.
#pragma unroll
    for (int i = 0; i < 8; i++) {
        int row = tr * 8 + i;
        int c = row & 15;
#pragma unroll
        for (int j = 0; j < 8; j++) {
            int f = tc * 8 + j;
            float v = acc[i][j];
            if (f <= c) v *= sm.rnf_s[f];
            sm.S[row][f] = v;
        }
    }
    __syncwarp();

    // ---- DTW DP (reference's row-parallel form), one warp per pair ----
    const int w = tid >> 5, lane = tid & 31;
    const float NEG = __int_as_float(0xff800000);  // -inf
    float Rp[4] = {NEG, NEG, NEG, NEG};            // D[i-1] at my 4 cols
    float p_prev = 0.0f;                            // padded col-0 of prev row
    float (*Srows)[128] = (float (*)[128]) & sm.S[w * 16][0];

    for (int i = 1; i <= 16; i++) {
        float4 sv = *(const float4*)&Srows[i - 1][lane * 4];
        // local inclusive cumsum
        float cl0 = sv.x, cl1 = cl0 + sv.y, cl2 = cl1 + sv.z, cl3 = cl2 + sv.w;
        float inc = cl3;
#pragma unroll
        for (int d = 1; d < 32; d <<= 1) {
            float tsh = __shfl_up_sync(0xffffffffu, inc, d);
            if (lane >= d) inc += tsh;
        }
        float ex = __shfl_up_sync(0xffffffffu, inc, 1);
        if (lane == 0) ex = 0.0f;
        float Cc0 = ex + cl0, Cc1 = ex + cl1, Cc2 = ex + cl2, Cc3 = ex + cl3;
        // A[j] = max(D[i-1,j], D[i-1,j-1])
        float rp_left = __shfl_up_sync(0xffffffffu, Rp[3], 1);
        if (lane == 0) rp_left = p_prev;
        float A0 = fmaxf(Rp[0], rp_left);
        float A1 = fmaxf(Rp[1], Rp[0]);
        float A2 = fmaxf(Rp[2], Rp[1]);
        float A3 = fmaxf(Rp[3], Rp[2]);
        // T = A - Cm1, local cummax
        float M0 = A0 - ex;
        float M1 = fmaxf(M0, A1 - Cc0);
        float M2 = fmaxf(M1, A2 - Cc1);
        float M3 = fmaxf(M2, A3 - Cc2);
        float mscan = M3;
#pragma unroll
        for (int d = 1; d < 32; d <<= 1) {
            float tsh = __shfl_up_sync(0xffffffffu, mscan, d);
            if (lane >= d) mscan = fmaxf(mscan, tsh);
        }
        float exm = __shfl_up_sync(0xffffffffu, mscan, 1);
        if (lane == 0) exm = NEG;
        float Rc[4];
        Rc[0] = Cc0 + fmaxf(M0, exm);
        Rc[1] = Cc1 + fmaxf(M1, exm);
        Rc[2] = Cc2 + fmaxf(M2, exm);
        Rc[3] = Cc3 + fmaxf(M3, exm);
        // mv = argmax(up, left, diag), first-max priority (matches jnp.argmax)
        float rc_left = __shfl_up_sync(0xffffffffu, Rc[3], 1);
        if (lane == 0) rc_left = NEG;  // padded col-0 of current row
        unsigned int byte = 0;
#pragma unroll
        for (int u = 0; u < 4; u++) {
            float up = Rp[u];
            float left = (u == 0) ? rc_left : Rc[u - 1];
            float dg = (u == 0) ? rp_left : Rp[u - 1];
            int m;
            if (up >= left && up >= dg) m = 0;
            else if (left >= dg) m = 1;
            else m = 2;
            byte |= (unsigned)m << (2 * u);
        }
        sm.mvb[w][i - 1][lane] = (unsigned char)byte;
        Rp[0] = Rc[0]; Rp[1] = Rc[1]; Rp[2] = Rc[2]; Rp[3] = Rc[3];
        p_prev = NEG;
    }
    __syncwarp();

    // Zero mask (reuse S slab), then lane 0 backtracks writing 1.0
    float4* mreg = (float4*)&Srows[0][0];
    for (int t2 = lane; t2 < 512; t2 += 32) mreg[t2] = make_float4(0.f, 0.f, 0.f, 0.f);
    __syncwarp();
    if (lane == 0) {
        int i = 16, j = 128;
        while (i > 0 && j > 0) {
            Srows[i - 1][j - 1] = 1.0f;
            unsigned int byte = sm.mvb[w][i - 1][(j - 1) >> 2];
            int m = (byte >> (2 * ((j - 1) & 3))) & 3;
            if (m == 0) i -= 1;
            else if (m == 1) j -= 1;
            else { i -= 1; j -= 1; }
        }
    }
    __syncwarp();

    // Coalesced store: out[m][n][c][f]
    int mglob = mblk * 8 + w;
    float* outp = out + (((size_t)mglob * 128 + n) * 16) * 128;
    const float4* srcp = (const float4*)&Srows[0][0];
    float4* dstp = (float4*)outp;
    for (int t2 = lane; t2 < 512; t2 += 32) dstp[t2] = srcp[t2];
}

// ---------------------------------------------------------------------------
extern "C" void kernel_launch(void* const* d_in, const int* in_sizes, int n_in,
                              void* d_out, int out_size) {
    const float* cf = (const float*)d_in[0];  // c_feats [128,16,512]
    const float* ff = (const float*)d_in[1];  // f_feats [128,128,512]
    float* out = (float*)d_out;               // [128,128,16,128] float32

    prep_norms<<<18432, 128>>>(cf, ff);
    {
        dim3 g(16, 64), b(32, 8);
        transpose_c<<<g, b>>>(cf);
    }
    {
        dim3 g(16, 4, 128), b(32, 8);
        transpose_f<<<g, b>>>(ff);
    }

    cudaFuncSetAttribute(dtw_kernel, cudaFuncAttributeMaxDynamicSharedMemorySize,
                         (int)sizeof(SmemLayout));
    dim3 grid(128, 16);
    dtw_kernel<<<grid, 256, (int)sizeof(SmemLayout)>>>(out);
}

// round 8
// speedup vs baseline: 1.2825x; 1.0505x over previous
#include <cuda_runtime.h>
#include <cstdint>

// Problem dims (fixed)
#define B_ 128
#define C_ 16
#define F_ 128
#define D_ 512

// Scratch (no allocation allowed)
__device__ float g_xnT[512 * 2048];        // normalized c_feats, TRANSPOSED: [k][m]
__device__ float g_ffT[128 * 512 * 128];   // f_feats transposed per n: [n][k][f]
__device__ float g_rnc[2048];              // 1/||c_feats row||
__device__ float g_rnf[128 * 128];         // 1/||f_feats[n,f]||

// ---------------------------------------------------------------------------
// Kernel A: reciprocal row norms for both tensors.
// ---------------------------------------------------------------------------
__global__ void prep_norms(const float* __restrict__ cf, const float* __restrict__ ff) {
    int row = blockIdx.x;
    int t = threadIdx.x;  // 128 threads, one float4 each
    const float* src = (row < 2048) ? (cf + (size_t)row * D_)
                                    : (ff + (size_t)(row - 2048) * D_);
    float4 v = ((const float4*)src)[t];
    float ss = v.x * v.x + v.y * v.y + v.z * v.z + v.w * v.w;
#pragma unroll
    for (int o = 16; o > 0; o >>= 1) ss += __shfl_xor_sync(0xffffffffu, ss, o);
    __shared__ float sred[4];
    if ((t & 31) == 0) sred[t >> 5] = ss;
    __syncthreads();
    if (t == 0) {
        float nrm = sqrtf(sred[0] + sred[1] + sred[2] + sred[3]);
        if (row < 2048) g_rnc[row] = 1.0f / nrm;
        else            g_rnf[row - 2048] = 1.0f / nrm;
    }
}

// ---------------------------------------------------------------------------
// Kernel B1: transpose + normalize c_feats -> g_xnT [512][2048]
// grid (16, 64), block (32, 8)
// ---------------------------------------------------------------------------
__global__ void transpose_c(const float* __restrict__ cf) {
    __shared__ float t[32][33];
    int kbase = blockIdx.x * 32, mbase = blockIdx.y * 32;
    int tx = threadIdx.x, ty = threadIdx.y;
#pragma unroll
    for (int i = 0; i < 4; i++) {
        int m = mbase + ty + i * 8;
        t[ty + i * 8][tx] = cf[(size_t)m * D_ + kbase + tx] * g_rnc[m];
    }
    __syncthreads();
#pragma unroll
    for (int i = 0; i < 4; i++) {
        g_xnT[(size_t)(kbase + ty + i * 8) * 2048 + mbase + tx] = t[tx][ty + i * 8];
    }
}

// ---------------------------------------------------------------------------
// Kernel B2: transpose f_feats per n -> g_ffT [n][512][128]
// grid (16, 4, 128), block (32, 8)
// ---------------------------------------------------------------------------
__global__ void transpose_f(const float* __restrict__ ff) {
    __shared__ float t[32][33];
    int kbase = blockIdx.x * 32, fbase = blockIdx.y * 32, n = blockIdx.z;
    int tx = threadIdx.x, ty = threadIdx.y;
    const float* fin = ff + (size_t)n * F_ * D_;
    float* fout = g_ffT + (size_t)n * D_ * F_;
#pragma unroll
    for (int i = 0; i < 4; i++) {
        t[ty + i * 8][tx] = fin[(size_t)(fbase + ty + i * 8) * D_ + kbase + tx];
    }
    __syncthreads();
#pragma unroll
    for (int i = 0; i < 4; i++) {
        fout[(size_t)(kbase + ty + i * 8) * F_ + fbase + tx] = t[tx][ty + i * 8];
    }
}

// ---------------------------------------------------------------------------
// Packed dual-lane fp32 FMA (Blackwell): d = a*b + c per 32-bit lane.
// Bit-exact vs two scalar FFMA.rn — DP decisions unchanged.
// ---------------------------------------------------------------------------
__device__ __forceinline__ void fma2(unsigned long long& d, unsigned long long a,
                                     unsigned long long b) {
    asm("fma.rn.f32x2 %0, %1, %2, %0;" : "+l"(d) : "l"(a), "l"(b));
}
__device__ __forceinline__ unsigned long long rep2(float x) {
    unsigned long long r;
    asm("mov.b64 %0, {%1, %1};" : "=l"(r) : "f"(x));
    return r;
}

// ---------------------------------------------------------------------------
// Kernel C: GEMM (cp.async double-buffered, f32x2 math) + per-pair DTW
// Grid: (n=128, mblk=16). Block 256 threads = 8 warps; warp w owns pair
// (m = mblk*8 + w, n).
// ---------------------------------------------------------------------------
struct SmemLayout {
    float As[2][16][128];              // 16 KB double-buffered (k-major)
    float Bs[2][16][128];              // 16 KB
    float S[128][128];                 // 64 KB: S tile, later reused as mask
    unsigned char mvb[8][16][32];      // 4 KB: 2-bit moves
    float rnf_s[16];
};

__device__ __forceinline__ void cp_async16(float* sp, const float* gp) {
    unsigned sa = (unsigned)__cvta_generic_to_shared(sp);
    asm volatile("cp.async.cg.shared.global [%0], [%1], 16;\n" ::"r"(sa), "l"(gp));
}

__global__ void __launch_bounds__(256, 2)
dtw_kernel(float* __restrict__ out) {
    extern __shared__ char smraw[];
    SmemLayout& sm = *reinterpret_cast<SmemLayout*>(smraw);

    const int tid = threadIdx.x;
    const int n = blockIdx.x, mblk = blockIdx.y;
    const int tr = tid >> 4, tc = tid & 15;

    if (tid < 16) sm.rnf_s[tid] = g_rnf[n * F_ + tid];

    const float* An = g_xnT + mblk * 128;              // + k*2048 + m
    const float* Bn = g_ffT + (size_t)n * D_ * F_;     // + k*128 + f

    // stage tile kt into buffer buf: 1024 16B segments, 4 per thread
    auto stage = [&](int buf, int kt) {
        const int kbase = kt * 16;
#pragma unroll
        for (int s = 0; s < 4; s++) {
            int idx = tid + s * 256;
            int r = idx >> 5;       // 0..31 (uniform per warp)
            int seg = idx & 31;     // 16B segment within a 512B row
            if (r < 16) {
                cp_async16(&sm.As[buf][r][seg * 4],
                           An + (size_t)(kbase + r) * 2048 + seg * 4);
            } else {
                int rr = r - 16;
                cp_async16(&sm.Bs[buf][rr][seg * 4],
                           Bn + (size_t)(kbase + rr) * 128 + seg * 4);
            }
        }
        asm volatile("cp.async.commit_group;\n" ::);
    };

    // Packed accumulators: acc2[i][j2] holds columns (tc*8+2*j2, +1) for row tr*8+i
    unsigned long long acc2[8][4];
#pragma unroll
    for (int i = 0; i < 8; i++)
#pragma unroll
        for (int j = 0; j < 4; j++) acc2[i][j] = 0ull;

    stage(0, 0);

    for (int kt = 0; kt < 32; kt++) {
        const int buf = kt & 1;
        if (kt + 1 < 32) {
            stage(buf ^ 1, kt + 1);
            asm volatile("cp.async.wait_group 1;\n" ::);
        } else {
            asm volatile("cp.async.wait_group 0;\n" ::);
        }
        __syncthreads();
#pragma unroll
        for (int k = 0; k < 16; k++) {
            float a[8];
            *(float4*)&a[0] = *(const float4*)&sm.As[buf][k][tr * 8];
            *(float4*)&a[4] = *(const float4*)&sm.As[buf][k][tr * 8 + 4];
            ulonglong2 b01 = *(const ulonglong2*)&sm.Bs[buf][k][tc * 8];
            ulonglong2 b23 = *(const ulonglong2*)&sm.Bs[buf][k][tc * 8 + 4];
#pragma unroll
            for (int i = 0; i < 8; i++) {
                unsigned long long ap = rep2(a[i]);
                fma2(acc2[i][0], ap, b01.x);
                fma2(acc2[i][1], ap, b01.y);
                fma2(acc2[i][2], ap, b23.x);
                fma2(acc2[i][3], ap, b23.y);
            }
        }
        __syncthreads();
    }

    // Epilogue: unpack, rescale (f<=c), store S. Each warp's rows stay within
    // its own 16-row slab (tr in {2w,2w+1}) -> only __syncwarp needed after.
#pragma unroll
    for (int i = 0; i < 8; i++) {
        int row = tr * 8 + i;
        int c = row & 15;
#pragma unroll
        for (int j2 = 0; j2 < 4; j2++) {
            float lo, hi;
            asm("mov.b64 {%0, %1}, %2;" : "=f"(lo), "=f"(hi) : "l"(acc2[i][j2]));
            int f = tc * 8 + j2 * 2;
            if (f <= c) lo *= sm.rnf_s[f];
            if (f + 1 <= c) hi *= sm.rnf_s[f + 1];
            float2 v; v.x = lo; v.y = hi;
            *(float2*)&sm.S[row][f] = v;
        }
    }
    __syncwarp();

    // ---- DTW DP (reference's row-parallel form), one warp per pair ----
    const int w = tid >> 5, lane = tid & 31;
    const float NEG = __int_as_float(0xff800000);  // -inf
    float Rp[4] = {NEG, NEG, NEG, NEG};            // D[i-1] at my 4 cols
    float p_prev = 0.0f;                            // padded col-0 of prev row
    float (*Srows)[128] = (float (*)[128]) & sm.S[w * 16][0];

    for (int i = 1; i <= 16; i++) {
        float4 sv = *(const float4*)&Srows[i - 1][lane * 4];
        // local inclusive cumsum
        float cl0 = sv.x, cl1 = cl0 + sv.y, cl2 = cl1 + sv.z, cl3 = cl2 + sv.w;
        float inc = cl3;
#pragma unroll
        for (int d = 1; d < 32; d <<= 1) {
            float tsh = __shfl_up_sync(0xffffffffu, inc, d);
            if (lane >= d) inc += tsh;
        }
        float ex = __shfl_up_sync(0xffffffffu, inc, 1);
        if (lane == 0) ex = 0.0f;
        float Cc0 = ex + cl0, Cc1 = ex + cl1, Cc2 = ex + cl2, Cc3 = ex + cl3;
        // A[j] = max(D[i-1,j], D[i-1,j-1])
        float rp_left = __shfl_up_sync(0xffffffffu, Rp[3], 1);
        if (lane == 0) rp_left = p_prev;
        float A0 = fmaxf(Rp[0], rp_left);
        float A1 = fmaxf(Rp[1], Rp[0]);
        float A2 = fmaxf(Rp[2], Rp[1]);
        float A3 = fmaxf(Rp[3], Rp[2]);
        // T = A - Cm1, local cummax
        float M0 = A0 - ex;
        float M1 = fmaxf(M0, A1 - Cc0);
        float M2 = fmaxf(M1, A2 - Cc1);
        float M3 = fmaxf(M2, A3 - Cc2);
        float mscan = M3;
#pragma unroll
        for (int d = 1; d < 32; d <<= 1) {
            float tsh = __shfl_up_sync(0xffffffffu, mscan, d);
            if (lane >= d) mscan = fmaxf(mscan, tsh);
        }
        float exm = __shfl_up_sync(0xffffffffu, mscan, 1);
        if (lane == 0) exm = NEG;
        float Rc[4];
        Rc[0] = Cc0 + fmaxf(M0, exm);
        Rc[1] = Cc1 + fmaxf(M1, exm);
        Rc[2] = Cc2 + fmaxf(M2, exm);
        Rc[3] = Cc3 + fmaxf(M3, exm);
        // mv = argmax(up, left, diag), first-max priority (matches jnp.argmax)
        float rc_left = __shfl_up_sync(0xffffffffu, Rc[3], 1);
        if (lane == 0) rc_left = NEG;  // padded col-0 of current row
        unsigned int byte = 0;
#pragma unroll
        for (int u = 0; u < 4; u++) {
            float up = Rp[u];
            float left = (u == 0) ? rc_left : Rc[u - 1];
            float dg = (u == 0) ? rp_left : Rp[u - 1];
            int m;
            if (up >= left && up >= dg) m = 0;
            else if (left >= dg) m = 1;
            else m = 2;
            byte |= (unsigned)m << (2 * u);
        }
        sm.mvb[w][i - 1][lane] = (unsigned char)byte;
        Rp[0] = Rc[0]; Rp[1] = Rc[1]; Rp[2] = Rc[2]; Rp[3] = Rc[3];
        p_prev = NEG;
    }
    __syncwarp();

    // Zero mask (reuse S slab), then lane 0 backtracks writing 1.0
    float4* mreg = (float4*)&Srows[0][0];
    for (int t2 = lane; t2 < 512; t2 += 32) mreg[t2] = make_float4(0.f, 0.f, 0.f, 0.f);
    __syncwarp();
    if (lane == 0) {
        int i = 16, j = 128;
        while (i > 0 && j > 0) {
            Srows[i - 1][j - 1] = 1.0f;
            unsigned int byte = sm.mvb[w][i - 1][(j - 1) >> 2];
            int m = (byte >> (2 * ((j - 1) & 3))) & 3;
            if (m == 0) i -= 1;
            else if (m == 1) j -= 1;
            else { i -= 1; j -= 1; }
        }
    }
    __syncwarp();

    // Coalesced store: out[m][n][c][f]
    int mglob = mblk * 8 + w;
    float* outp = out + (((size_t)mglob * 128 + n) * 16) * 128;
    const float4* srcp = (const float4*)&Srows[0][0];
    float4* dstp = (float4*)outp;
    for (int t2 = lane; t2 < 512; t2 += 32) dstp[t2] = srcp[t2];
}

// ---------------------------------------------------------------------------
extern "C" void kernel_launch(void* const* d_in, const int* in_sizes, int n_in,
                              void* d_out, int out_size) {
    const float* cf = (const float*)d_in[0];  // c_feats [128,16,512]
    const float* ff = (const float*)d_in[1];  // f_feats [128,128,512]
    float* out = (float*)d_out;               // [128,128,16,128] float32

    prep_norms<<<18432, 128>>>(cf, ff);
    {
        dim3 g(16, 64), b(32, 8);
        transpose_c<<<g, b>>>(cf);
    }
    {
        dim3 g(16, 4, 128), b(32, 8);
        transpose_f<<<g, b>>>(ff);
    }

    cudaFuncSetAttribute(dtw_kernel, cudaFuncAttributeMaxDynamicSharedMemorySize,
                         (int)sizeof(SmemLayout));
    dim3 grid(128, 16);
    dtw_kernel<<<grid, 256, (int)sizeof(SmemLayout)>>>(out);
}

// round 9
// speedup vs baseline: 1.3020x; 1.0152x over previous
#include <cuda_runtime.h>
#include <cstdint>

// Problem dims (fixed)
#define B_ 128
#define C_ 16
#define F_ 128
#define D_ 512

// Scratch (no allocation allowed)
__device__ float g_xnT[512 * 2048];        // normalized c_feats, TRANSPOSED: [k][m]
__device__ float g_ffT[128 * 512 * 128];   // f_feats transposed per n: [n][k][f]
__device__ float g_rnc[2048];              // 1/||c_feats row||
__device__ float g_rnf[128 * 128];         // 1/||f_feats[n,f]||

// ---------------------------------------------------------------------------
// Kernel A: reciprocal row norms for both tensors.
// ---------------------------------------------------------------------------
__global__ void prep_norms(const float* __restrict__ cf, const float* __restrict__ ff) {
    int row = blockIdx.x;
    int t = threadIdx.x;  // 128 threads, one float4 each
    const float* src = (row < 2048) ? (cf + (size_t)row * D_)
                                    : (ff + (size_t)(row - 2048) * D_);
    float4 v = ((const float4*)src)[t];
    float ss = v.x * v.x + v.y * v.y + v.z * v.z + v.w * v.w;
#pragma unroll
    for (int o = 16; o > 0; o >>= 1) ss += __shfl_xor_sync(0xffffffffu, ss, o);
    __shared__ float sred[4];
    if ((t & 31) == 0) sred[t >> 5] = ss;
    __syncthreads();
    if (t == 0) {
        float nrm = sqrtf(sred[0] + sred[1] + sred[2] + sred[3]);
        if (row < 2048) g_rnc[row] = 1.0f / nrm;
        else            g_rnf[row - 2048] = 1.0f / nrm;
    }
}

// ---------------------------------------------------------------------------
// Kernel B1: transpose + normalize c_feats -> g_xnT [512][2048]
// ---------------------------------------------------------------------------
__global__ void transpose_c(const float* __restrict__ cf) {
    __shared__ float t[32][33];
    int kbase = blockIdx.x * 32, mbase = blockIdx.y * 32;
    int tx = threadIdx.x, ty = threadIdx.y;
#pragma unroll
    for (int i = 0; i < 4; i++) {
        int m = mbase + ty + i * 8;
        t[ty + i * 8][tx] = cf[(size_t)m * D_ + kbase + tx] * g_rnc[m];
    }
    __syncthreads();
#pragma unroll
    for (int i = 0; i < 4; i++) {
        g_xnT[(size_t)(kbase + ty + i * 8) * 2048 + mbase + tx] = t[tx][ty + i * 8];
    }
}

// ---------------------------------------------------------------------------
// Kernel B2: transpose f_feats per n -> g_ffT [n][512][128]
// ---------------------------------------------------------------------------
__global__ void transpose_f(const float* __restrict__ ff) {
    __shared__ float t[32][33];
    int kbase = blockIdx.x * 32, fbase = blockIdx.y * 32, n = blockIdx.z;
    int tx = threadIdx.x, ty = threadIdx.y;
    const float* fin = ff + (size_t)n * F_ * D_;
    float* fout = g_ffT + (size_t)n * D_ * F_;
#pragma unroll
    for (int i = 0; i < 4; i++) {
        t[ty + i * 8][tx] = fin[(size_t)(fbase + ty + i * 8) * D_ + kbase + tx];
    }
    __syncthreads();
#pragma unroll
    for (int i = 0; i < 4; i++) {
        fout[(size_t)(kbase + ty + i * 8) * F_ + fbase + tx] = t[tx][ty + i * 8];
    }
}

// ---------------------------------------------------------------------------
// Packed dual-lane fp32 FMA — bit-exact vs two scalar FFMA.rn.
// ---------------------------------------------------------------------------
__device__ __forceinline__ void fma2(unsigned long long& d, unsigned long long a,
                                     unsigned long long b) {
    asm("fma.rn.f32x2 %0, %1, %2, %0;" : "+l"(d) : "l"(a), "l"(b));
}
__device__ __forceinline__ unsigned long long rep2(float x) {
    unsigned long long r;
    asm("mov.b64 %0, {%1, %1};" : "=l"(r) : "f"(x));
    return r;
}

__device__ __forceinline__ void cp_async16(float* sp, const float* gp) {
    unsigned sa = (unsigned)__cvta_generic_to_shared(sp);
    asm volatile("cp.async.cg.shared.global [%0], [%1], 16;\n" ::"r"(sa), "l"(gp));
}

// ---------------------------------------------------------------------------
// Kernel C: GEMM (3-stage cp.async, 1 barrier/tile, f32x2) + per-pair DTW
// Grid: (n=128, mblk=16). Block 256 threads = 8 warps; warp w owns pair
// (m = mblk*8 + w, n).
//
// Smem layout (union):
//   [0,      49152)  3 stage buffers: stage s at s*16384 (As 8KB | Bs 8KB)
//   [0,      65536)  S[128][128]  (aliases stages; live only after mainloop)
//   [65536,  69632)  mvb: 8 warps x 512 B of 2-bit moves
//   [69632,  69696)  rnf_s[16]
// ---------------------------------------------------------------------------
static constexpr int STG_SZ = 16384;
static constexpr int MVB_OFF = 65536;
static constexpr int RNF_OFF = 69632;
static constexpr int SMEM_TOTAL = 69760;

__global__ void __launch_bounds__(256, 2)
dtw_kernel(float* __restrict__ out) {
    extern __shared__ char smem[];
    float* Sf = (float*)smem;
    float* rnf_s = (float*)(smem + RNF_OFF);

    const int tid = threadIdx.x;
    const int n = blockIdx.x, mblk = blockIdx.y;
    const int tr = tid >> 4, tc = tid & 15;

    if (tid < 16) rnf_s[tid] = g_rnf[n * F_ + tid];

    const float* An = g_xnT + mblk * 128;              // + k*2048 + m
    const float* Bn = g_ffT + (size_t)n * D_ * F_;     // + k*128 + f

    // stage tile kt into stage buffer s: 1024 16B segments, 4 per thread
    auto stage = [&](int s, int kt) {
        float* As = (float*)(smem + s * STG_SZ);
        float* Bs = As + 2048;
        const int kbase = kt * 16;
#pragma unroll
        for (int i = 0; i < 4; i++) {
            int idx = tid + i * 256;
            int r = idx >> 5;       // 0..31
            int seg = idx & 31;     // 16B segment within a 512B row
            if (r < 16) {
                cp_async16(As + r * 128 + seg * 4,
                           An + (size_t)(kbase + r) * 2048 + seg * 4);
            } else {
                int rr = r - 16;
                cp_async16(Bs + rr * 128 + seg * 4,
                           Bn + (size_t)(kbase + rr) * 128 + seg * 4);
            }
        }
        asm volatile("cp.async.commit_group;\n" ::);
    };

    // Packed accumulators: acc2[i][j2] = cols (tc*8+2*j2, +1) for row tr*8+i
    unsigned long long acc2[8][4];
#pragma unroll
    for (int i = 0; i < 8; i++)
#pragma unroll
        for (int j = 0; j < 4; j++) acc2[i][j] = 0ull;

    stage(0, 0);
    stage(1, 1);

    int s = 0;
    for (int kt = 0; kt < 32; kt++) {
        if (kt == 31) asm volatile("cp.async.wait_group 0;\n" ::);
        else          asm volatile("cp.async.wait_group 1;\n" ::);
        __syncthreads();
        // stage kt+2 into buffer (s+2)%3 == (kt-1)%3: provably idle (the
        // barrier above guarantees every warp finished compute(kt-1)).
        if (kt < 30) {
            int s2 = s + 2; if (s2 >= 3) s2 -= 3;
            stage(s2, kt + 2);
        }
        const float* As = (const float*)(smem + s * STG_SZ);
        const float* Bs = As + 2048;
#pragma unroll
        for (int k = 0; k < 16; k++) {
            float a[8];
            *(float4*)&a[0] = *(const float4*)&As[k * 128 + tr * 8];
            *(float4*)&a[4] = *(const float4*)&As[k * 128 + tr * 8 + 4];
            ulonglong2 b01 = *(const ulonglong2*)&Bs[k * 128 + tc * 8];
            ulonglong2 b23 = *(const ulonglong2*)&Bs[k * 128 + tc * 8 + 4];
#pragma unroll
            for (int i = 0; i < 8; i++) {
                unsigned long long ap = rep2(a[i]);
                fma2(acc2[i][0], ap, b01.x);
                fma2(acc2[i][1], ap, b01.y);
                fma2(acc2[i][2], ap, b23.x);
                fma2(acc2[i][3], ap, b23.y);
            }
        }
        s = (s + 1 == 3) ? 0 : s + 1;
    }
    __syncthreads();  // all computes done -> stage buffers dead, S may be written

    // Epilogue: unpack, rescale (f<=c), store S. Each warp's rows stay within
    // its own 16-row slab (tr in {2w,2w+1}) -> only __syncwarp needed after.
#pragma unroll
    for (int i = 0; i < 8; i++) {
        int row = tr * 8 + i;
        int c = row & 15;
#pragma unroll
        for (int j2 = 0; j2 < 4; j2++) {
            float lo, hi;
            asm("mov.b64 {%0, %1}, %2;" : "=f"(lo), "=f"(hi) : "l"(acc2[i][j2]));
            int f = tc * 8 + j2 * 2;
            if (f <= c) lo *= rnf_s[f];
            if (f + 1 <= c) hi *= rnf_s[f + 1];
            float2 v; v.x = lo; v.y = hi;
            *(float2*)&Sf[row * 128 + f] = v;
        }
    }
    __syncwarp();

    // ---- DTW DP (reference's row-parallel form), one warp per pair ----
    const int w = tid >> 5, lane = tid & 31;
    const float NEG = __int_as_float(0xff800000);  // -inf
    float Rp[4] = {NEG, NEG, NEG, NEG};            // D[i-1] at my 4 cols
    float p_prev = 0.0f;                            // padded col-0 of prev row
    float* Srows = Sf + w * 16 * 128;
    unsigned char* mvb = (unsigned char*)(smem + MVB_OFF) + w * 512;

    for (int i = 1; i <= 16; i++) {
        float4 sv = *(const float4*)&Srows[(i - 1) * 128 + lane * 4];
        // local inclusive cumsum
        float cl0 = sv.x, cl1 = cl0 + sv.y, cl2 = cl1 + sv.z, cl3 = cl2 + sv.w;
        float inc = cl3;
#pragma unroll
        for (int d = 1; d < 32; d <<= 1) {
            float tsh = __shfl_up_sync(0xffffffffu, inc, d);
            if (lane >= d) inc += tsh;
        }
        float ex = __shfl_up_sync(0xffffffffu, inc, 1);
        if (lane == 0) ex = 0.0f;
        float Cc0 = ex + cl0, Cc1 = ex + cl1, Cc2 = ex + cl2, Cc3 = ex + cl3;
        // A[j] = max(D[i-1,j], D[i-1,j-1])
        float rp_left = __shfl_up_sync(0xffffffffu, Rp[3], 1);
        if (lane == 0) rp_left = p_prev;
        float A0 = fmaxf(Rp[0], rp_left);
        float A1 = fmaxf(Rp[1], Rp[0]);
        float A2 = fmaxf(Rp[2], Rp[1]);
        float A3 = fmaxf(Rp[3], Rp[2]);
        // T = A - Cm1, local cummax
        float M0 = A0 - ex;
        float M1 = fmaxf(M0, A1 - Cc0);
        float M2 = fmaxf(M1, A2 - Cc1);
        float M3 = fmaxf(M2, A3 - Cc2);
        float mscan = M3;
#pragma unroll
        for (int d = 1; d < 32; d <<= 1) {
            float tsh = __shfl_up_sync(0xffffffffu, mscan, d);
            if (lane >= d) mscan = fmaxf(mscan, tsh);
        }
        float exm = __shfl_up_sync(0xffffffffu, mscan, 1);
        if (lane == 0) exm = NEG;
        float Rc[4];
        Rc[0] = Cc0 + fmaxf(M0, exm);
        Rc[1] = Cc1 + fmaxf(M1, exm);
        Rc[2] = Cc2 + fmaxf(M2, exm);
        Rc[3] = Cc3 + fmaxf(M3, exm);
        // mv = argmax(up, left, diag), first-max priority (matches jnp.argmax)
        float rc_left = __shfl_up_sync(0xffffffffu, Rc[3], 1);
        if (lane == 0) rc_left = NEG;  // padded col-0 of current row
        unsigned int byte = 0;
#pragma unroll
        for (int u = 0; u < 4; u++) {
            float up = Rp[u];
            float left = (u == 0) ? rc_left : Rc[u - 1];
            float dg = (u == 0) ? rp_left : Rp[u - 1];
            int m;
            if (up >= left && up >= dg) m = 0;
            else if (left >= dg) m = 1;
            else m = 2;
            byte |= (unsigned)m << (2 * u);
        }
        mvb[(i - 1) * 32 + lane] = (unsigned char)byte;
        Rp[0] = Rc[0]; Rp[1] = Rc[1]; Rp[2] = Rc[2]; Rp[3] = Rc[3];
        p_prev = NEG;
    }
    __syncwarp();

    // Zero mask (reuse S slab), then lane 0 backtracks writing 1.0
    float4* mreg = (float4*)Srows;
    for (int t2 = lane; t2 < 512; t2 += 32) mreg[t2] = make_float4(0.f, 0.f, 0.f, 0.f);
    __syncwarp();
    if (lane == 0) {
        int i = 16, j = 128;
        while (i > 0 && j > 0) {
            Srows[(i - 1) * 128 + (j - 1)] = 1.0f;
            unsigned int byte = mvb[(i - 1) * 32 + ((j - 1) >> 2)];
            int m = (byte >> (2 * ((j - 1) & 3))) & 3;
            if (m == 0) i -= 1;
            else if (m == 1) j -= 1;
            else { i -= 1; j -= 1; }
        }
    }
    __syncwarp();

    // Coalesced store: out[m][n][c][f]
    int mglob = mblk * 8 + w;
    float* outp = out + (((size_t)mglob * 128 + n) * 16) * 128;
    const float4* srcp = (const float4*)Srows;
    float4* dstp = (float4*)outp;
    for (int t2 = lane; t2 < 512; t2 += 32) dstp[t2] = srcp[t2];
}

// ---------------------------------------------------------------------------
extern "C" void kernel_launch(void* const* d_in, const int* in_sizes, int n_in,
                              void* d_out, int out_size) {
    const float* cf = (const float*)d_in[0];  // c_feats [128,16,512]
    const float* ff = (const float*)d_in[1];  // f_feats [128,128,512]
    float* out = (float*)d_out;               // [128,128,16,128] float32

    prep_norms<<<18432, 128>>>(cf, ff);
    {
        dim3 g(16, 64), b(32, 8);
        transpose_c<<<g, b>>>(cf);
    }
    {
        dim3 g(16, 4, 128), b(32, 8);
        transpose_f<<<g, b>>>(ff);
    }

    cudaFuncSetAttribute(dtw_kernel, cudaFuncAttributeMaxDynamicSharedMemorySize,
                         SMEM_TOTAL);
    dim3 grid(128, 16);
    dtw_kernel<<<grid, 256, SMEM_TOTAL>>>(out);
}